// round 2
// baseline (speedup 1.0000x reference)
#include <cuda_runtime.h>
#include <cstdint>

#define B_ 64
#define N_ 32
#define H_ 24
#define F_ 256

typedef unsigned long long u64;

// Scratch (device globals: no allocations allowed)
__device__ float g_QWq[(size_t)B_ * N_ * F_];            // 2 MB
__device__ float g_logits[(size_t)B_ * N_ * H_];         // 196 KB
__device__ float g_VWv[(size_t)B_ * N_ * H_ * F_];       // 50 MB

// ---------------- f32x2 packed-math helpers ----------------
__device__ __forceinline__ u64 pack2(float x, float y) {
    u64 r; asm("mov.b64 %0, {%1,%2};" : "=l"(r) : "f"(x), "f"(y)); return r;
}
__device__ __forceinline__ void unpack2(u64 v, float& x, float& y) {
    asm("mov.b64 {%0,%1}, %2;" : "=f"(x), "=f"(y) : "l"(v));
}
__device__ __forceinline__ void fma2(u64& d, u64 a, u64 b) {
    asm("fma.rn.f32x2 %0, %1, %2, %0;" : "+l"(d) : "l"(a), "l"(b));
}

// ---------------- cp.async helpers ----------------
__device__ __forceinline__ uint32_t s2u(const void* p) {
    return (uint32_t)__cvta_generic_to_shared(p);
}
__device__ __forceinline__ void cpasync16(uint32_t dst, const void* src) {
    asm volatile("cp.async.cg.shared.global [%0], [%1], 16;" :: "r"(dst), "l"(src));
}
__device__ __forceinline__ void cpcommit() { asm volatile("cp.async.commit_group;"); }
__device__ __forceinline__ void cpwaitall() { asm volatile("cp.async.wait_all;" ::: "memory"); }

// ---------------- SMEM staging ----------------
// Ad: A chunk transposed AND duplicated: Ad[f][2*b] = Ad[f][2*b+1] = A[b][f]
//     so a warp-broadcast LDS.128 yields ready-made {a,a} pairs for fma2.
// Ws: W chunk natural layout Ws[f][g]; pairs along g feed fma2's b operand.
struct __align__(16) Smem {
    float Ad[2][16][128];   // 16 KB
    float Ws[2][16][256];   // 32 KB
};                          // 48 KB total (static limit)

// ---------------- Core: C[64x256] = A[64x256] @ W[256x256] ----------------
// 256 threads, 8x8 microtile per thread. Thread t: warp tb=t>>5 owns rows
// tb*8..tb*8+7; lane tg=t&31 owns cols tg*8..tg*8+7. acc[i][j2] packs
// {C[i][2j2], C[i][2j2+1]} as f32x2.
__device__ __forceinline__ void gemm_tile(const float* __restrict__ Abase, long strideA,
                                          const float* __restrict__ Wbase,
                                          Smem* sm, u64 acc[8][4])
{
    const int t  = threadIdx.x;
    const int ar = t >> 2;          // A row 0..63
    const int ac = (t & 3) << 2;    // f offset 0,4,8,12 within chunk
    const int wf = t >> 4;          // W chunk row 0..15
    const int wg = (t & 15) << 4;   // W col 0..240
    const int tb = t >> 5;
    const int tg = t & 31;

    #pragma unroll
    for (int i = 0; i < 8; i++)
        #pragma unroll
        for (int j = 0; j < 4; j++) acc[i][j] = 0ULL;

    const float* aPtr = Abase + (long)ar * strideA + ac;
    const float* wPtr = Wbase + (long)wf * F_ + wg;

    // Prologue: stage chunk 0 into buffer 0
    float4 aReg = *(const float4*)aPtr;
    {
        uint32_t wd = s2u(&sm->Ws[0][wf][wg]);
        cpasync16(wd,      wPtr);
        cpasync16(wd + 16, wPtr + 4);
        cpasync16(wd + 32, wPtr + 8);
        cpasync16(wd + 48, wPtr + 12);
        cpcommit();
        u64* AdU = (u64*)sm->Ad[0];
        AdU[(ac + 0) * 64 + ar] = pack2(aReg.x, aReg.x);
        AdU[(ac + 1) * 64 + ar] = pack2(aReg.y, aReg.y);
        AdU[(ac + 2) * 64 + ar] = pack2(aReg.z, aReg.z);
        AdU[(ac + 3) * 64 + ar] = pack2(aReg.w, aReg.w);
    }
    cpwaitall();
    __syncthreads();

    #pragma unroll 2
    for (int c = 0; c < 16; ++c) {
        const int cur = c & 1;
        const int nxt = cur ^ 1;
        if (c + 1 < 16) {   // issue next chunk's loads (latency hidden by compute)
            aReg = *(const float4*)(aPtr + (c + 1) * 16);
            const float* wp = wPtr + (long)(c + 1) * 16 * F_;
            uint32_t wd = s2u(&sm->Ws[nxt][wf][wg]);
            cpasync16(wd,      wp);
            cpasync16(wd + 16, wp + 4);
            cpasync16(wd + 32, wp + 8);
            cpasync16(wd + 48, wp + 12);
            cpcommit();
        }
        const u64* AdU = (const u64*)sm->Ad[cur];
        const u64* WsU = (const u64*)sm->Ws[cur];
        #pragma unroll
        for (int f = 0; f < 16; ++f) {
            u64 ad[8], bs[4];
            const ulonglong2* ap2 = (const ulonglong2*)(AdU + f * 64 + tb * 8);
            ulonglong2 v0 = ap2[0], v1 = ap2[1], v2 = ap2[2], v3 = ap2[3];
            ad[0] = v0.x; ad[1] = v0.y; ad[2] = v1.x; ad[3] = v1.y;
            ad[4] = v2.x; ad[5] = v2.y; ad[6] = v3.x; ad[7] = v3.y;
            const ulonglong2* bp2 = (const ulonglong2*)(WsU + f * 128 + tg * 4);
            ulonglong2 w0 = bp2[0], w1 = bp2[1];
            bs[0] = w0.x; bs[1] = w0.y; bs[2] = w1.x; bs[3] = w1.y;
            #pragma unroll
            for (int i = 0; i < 8; i++) {
                fma2(acc[i][0], ad[i], bs[0]);
                fma2(acc[i][1], ad[i], bs[1]);
                fma2(acc[i][2], ad[i], bs[2]);
                fma2(acc[i][3], ad[i], bs[3]);
            }
        }
        if (c + 1 < 16) {
            u64* AdU2 = (u64*)sm->Ad[nxt];
            AdU2[(ac + 0) * 64 + ar] = pack2(aReg.x, aReg.x);
            AdU2[(ac + 1) * 64 + ar] = pack2(aReg.y, aReg.y);
            AdU2[(ac + 2) * 64 + ar] = pack2(aReg.z, aReg.z);
            AdU2[(ac + 3) * 64 + ar] = pack2(aReg.w, aReg.w);
            cpwaitall();
        }
        __syncthreads();
    }
}

__device__ __forceinline__ void unpack8(const u64 a[4], float c[8]) {
    unpack2(a[0], c[0], c[1]);
    unpack2(a[1], c[2], c[3]);
    unpack2(a[2], c[4], c[5]);
    unpack2(a[3], c[6], c[7]);
}

// ---------------- K1: QWq[b,n,g] = Q[b,n,:]@Wq[n] + bq[n,:] ----------------
__global__ void __launch_bounds__(256, 2) k_qwq(const float* __restrict__ Q,
                                                const float* __restrict__ Wq,
                                                const float* __restrict__ bq)
{
    __shared__ Smem sm;
    const int n = blockIdx.x;
    u64 acc[8][4];
    gemm_tile(Q + (size_t)n * F_, (long)N_ * F_, Wq + (size_t)n * F_ * F_, &sm, acc);
    const int t = threadIdx.x, tb = t >> 5, tg = t & 31;
    const float* bqp = bq + (size_t)n * F_ + tg * 8;
    float4 b0 = *(const float4*)bqp, b1 = *(const float4*)(bqp + 4);
    #pragma unroll
    for (int i = 0; i < 8; i++) {
        float c[8]; unpack8(acc[i], c);
        float4 o0 = make_float4(c[0] + b0.x, c[1] + b0.y, c[2] + b0.z, c[3] + b0.w);
        float4 o1 = make_float4(c[4] + b1.x, c[5] + b1.y, c[6] + b1.z, c[7] + b1.w);
        float* op = g_QWq + ((size_t)(tb * 8 + i) * N_ + n) * F_ + tg * 8;
        *(float4*)op = o0; *(float4*)(op + 4) = o1;
    }
}

// ---------------- K2: per (h,n) CTA: logits + VWv ----------------
__global__ void __launch_bounds__(256, 2) k_kv(const float* __restrict__ Kt,
                                               const float* __restrict__ Vt,
                                               const float* __restrict__ Wk,
                                               const float* __restrict__ bk,
                                               const float* __restrict__ Wv,
                                               const float* __restrict__ bv)
{
    __shared__ Smem sm;
    const int h = blockIdx.x, n = blockIdx.y;
    const int t = threadIdx.x, tb = t >> 5, tg = t & 31;
    u64 acc[8][4];

    // ---- Phase 1: C = K[:,h,n,:] @ Wk[n,h]; logits = rowdot(C+bk, QWq) ----
    gemm_tile(Kt + ((size_t)h * N_ + n) * F_, (long)H_ * N_ * F_,
              Wk + ((size_t)n * H_ + h) * F_ * F_, &sm, acc);
    {
        const float* bkp = bk + ((size_t)n * H_ + h) * F_ + tg * 8;
        float4 k0 = *(const float4*)bkp, k1 = *(const float4*)(bkp + 4);
        float part[8];
        #pragma unroll
        for (int i = 0; i < 8; i++) {
            float c[8]; unpack8(acc[i], c);
            const float* qp = g_QWq + ((size_t)(tb * 8 + i) * N_ + n) * F_ + tg * 8;
            float4 q0 = *(const float4*)qp, q1 = *(const float4*)(qp + 4);
            part[i] = (c[0] + k0.x) * q0.x + (c[1] + k0.y) * q0.y
                    + (c[2] + k0.z) * q0.z + (c[3] + k0.w) * q0.w
                    + (c[4] + k1.x) * q1.x + (c[5] + k1.y) * q1.y
                    + (c[6] + k1.z) * q1.z + (c[7] + k1.w) * q1.w;
        }
        #pragma unroll
        for (int off = 16; off > 0; off >>= 1)
            #pragma unroll
            for (int i = 0; i < 8; i++)
                part[i] += __shfl_xor_sync(0xffffffffu, part[i], off);
        if (tg == 0) {
            #pragma unroll
            for (int i = 0; i < 8; i++)
                g_logits[((size_t)(tb * 8 + i) * N_ + n) * H_ + h] = part[i];
        }
    }
    __syncthreads();

    // ---- Phase 2: VWv[b,n,h,:] = V[:,h,n,:] @ Wv[n,h] + bv ----
    gemm_tile(Vt + ((size_t)h * N_ + n) * F_, (long)H_ * N_ * F_,
              Wv + ((size_t)n * H_ + h) * F_ * F_, &sm, acc);
    {
        const float* bvp = bv + ((size_t)n * H_ + h) * F_ + tg * 8;
        float4 v0 = *(const float4*)bvp, v1 = *(const float4*)(bvp + 4);
        #pragma unroll
        for (int i = 0; i < 8; i++) {
            float c[8]; unpack8(acc[i], c);
            float4 o0 = make_float4(c[0] + v0.x, c[1] + v0.y, c[2] + v0.z, c[3] + v0.w);
            float4 o1 = make_float4(c[4] + v1.x, c[5] + v1.y, c[6] + v1.z, c[7] + v1.w);
            float* op = g_VWv + (((size_t)(tb * 8 + i) * N_ + n) * H_ + h) * F_ + tg * 8;
            *(float4*)op = o0; *(float4*)(op + 4) = o1;
        }
    }
}

// ---------------- K3: softmax over H; write scores to d_out ----------------
__global__ void k_softmax(float* __restrict__ out)
{
    const int idx = blockIdx.x * 256 + threadIdx.x;   // (b*N+n), 0..2047
    const float* lp = g_logits + (size_t)idx * H_;
    float l[H_];
    float m = -3.4e38f;
    #pragma unroll
    for (int h = 0; h < H_; ++h) { l[h] = lp[h]; m = fmaxf(m, l[h]); }
    float s = 0.f;
    #pragma unroll
    for (int h = 0; h < H_; ++h) { l[h] = expf(l[h] - m); s += l[h]; }
    const float inv = 1.0f / s;
    float* sp = out + (size_t)B_ * N_ * F_ + (size_t)idx * H_;
    #pragma unroll
    for (int h = 0; h < H_; ++h) sp[h] = l[h] * inv;
}

// ---------------- K4: heads[b,n,g] = sum_h scores * VWv ----------------
__global__ void k_heads(float* __restrict__ out)
{
    __shared__ float s[H_];
    const int bn = blockIdx.x;          // b*N+n
    const int g = threadIdx.x;          // 0..255
    if (g < H_) s[g] = out[(size_t)B_ * N_ * F_ + (size_t)bn * H_ + g];
    __syncthreads();
    const float* vp = g_VWv + (size_t)bn * H_ * F_ + g;
    float acc = 0.f;
    #pragma unroll
    for (int h = 0; h < H_; ++h) acc += s[h] * vp[(size_t)h * F_];
    out[(size_t)bn * F_ + g] = acc;
}

// ---------------- Launch ----------------
extern "C" void kernel_launch(void* const* d_in, const int* in_sizes, int n_in,
                              void* d_out, int out_size)
{
    (void)in_sizes; (void)n_in; (void)out_size;
    const float* Q  = (const float*)d_in[0];
    const float* K  = (const float*)d_in[1];
    const float* V  = (const float*)d_in[2];
    const float* Wq = (const float*)d_in[3];
    const float* bq = (const float*)d_in[4];
    const float* Wk = (const float*)d_in[5];
    const float* bk = (const float*)d_in[6];
    const float* Wv = (const float*)d_in[7];
    const float* bv = (const float*)d_in[8];
    float* out = (float*)d_out;

    k_qwq<<<N_, 256>>>(Q, Wq, bq);
    k_kv<<<dim3(H_, N_), 256>>>(K, V, Wk, bk, Wv, bv);
    k_softmax<<<(B_ * N_) / 256, 256>>>(out);
    k_heads<<<B_ * N_, 256>>>(out);
}

// round 3
// speedup vs baseline: 1.0003x; 1.0003x over previous
#include <cuda_runtime.h>
#include <cstdint>

#define B_ 64
#define N_ 32
#define H_ 24
#define F_ 256

typedef unsigned long long u64;

// Scratch (device globals: no allocations allowed)
__device__ float g_QWq[(size_t)B_ * N_ * F_];            // 2 MB
__device__ float g_logits[(size_t)B_ * N_ * H_];         // 196 KB
__device__ float g_VWv[(size_t)B_ * N_ * H_ * F_];       // 50 MB

// ---------------- f32x2 packed-math helpers ----------------
__device__ __forceinline__ u64 pack2(float x, float y) {
    u64 r; asm("mov.b64 %0, {%1,%2};" : "=l"(r) : "f"(x), "f"(y)); return r;
}
__device__ __forceinline__ void unpack2(u64 v, float& x, float& y) {
    asm("mov.b64 {%0,%1}, %2;" : "=f"(x), "=f"(y) : "l"(v));
}
__device__ __forceinline__ void fma2(u64& d, u64 a, u64 b) {
    asm("fma.rn.f32x2 %0, %1, %2, %0;" : "+l"(d) : "l"(a), "l"(b));
}

// ---------------- cp.async helpers ----------------
__device__ __forceinline__ uint32_t s2u(const void* p) {
    return (uint32_t)__cvta_generic_to_shared(p);
}
__device__ __forceinline__ void cpasync16(uint32_t dst, const void* src) {
    asm volatile("cp.async.cg.shared.global [%0], [%1], 16;" :: "r"(dst), "l"(src));
}
__device__ __forceinline__ void cpcommit() { asm volatile("cp.async.commit_group;"); }
__device__ __forceinline__ void cpwaitall() { asm volatile("cp.async.wait_all;" ::: "memory"); }

// ---------------- SMEM staging ----------------
// Ad: A chunk transposed AND duplicated: Ad[f][2*b] = Ad[f][2*b+1] = A[b][f]
//     so a warp-broadcast LDS.128 yields ready-made {a,a} pairs for fma2.
// Ws: W chunk natural layout Ws[f][g]; pairs along g feed fma2's b operand.
struct __align__(16) Smem {
    float Ad[2][16][128];   // 16 KB
    float Ws[2][16][256];   // 32 KB
};                          // 48 KB total (static limit)

// ---------------- Core: C[64x256] = A[64x256] @ W[256x256] ----------------
// 256 threads, 8x8 microtile per thread. Thread t: warp tb=t>>5 owns rows
// tb*8..tb*8+7; lane tg=t&31 owns cols tg*8..tg*8+7. acc[i][j2] packs
// {C[i][2j2], C[i][2j2+1]} as f32x2.
__device__ __forceinline__ void gemm_tile(const float* __restrict__ Abase, long strideA,
                                          const float* __restrict__ Wbase,
                                          Smem* sm, u64 acc[8][4])
{
    const int t  = threadIdx.x;
    const int ar = t >> 2;          // A row 0..63
    const int ac = (t & 3) << 2;    // f offset 0,4,8,12 within chunk
    const int wf = t >> 4;          // W chunk row 0..15
    const int wg = (t & 15) << 4;   // W col 0..240
    const int tb = t >> 5;
    const int tg = t & 31;

    #pragma unroll
    for (int i = 0; i < 8; i++)
        #pragma unroll
        for (int j = 0; j < 4; j++) acc[i][j] = 0ULL;

    const float* aPtr = Abase + (long)ar * strideA + ac;
    const float* wPtr = Wbase + (long)wf * F_ + wg;

    // Prologue: stage chunk 0 into buffer 0
    float4 aReg = *(const float4*)aPtr;
    {
        uint32_t wd = s2u(&sm->Ws[0][wf][wg]);
        cpasync16(wd,      wPtr);
        cpasync16(wd + 16, wPtr + 4);
        cpasync16(wd + 32, wPtr + 8);
        cpasync16(wd + 48, wPtr + 12);
        cpcommit();
        u64* AdU = (u64*)sm->Ad[0];
        AdU[(ac + 0) * 64 + ar] = pack2(aReg.x, aReg.x);
        AdU[(ac + 1) * 64 + ar] = pack2(aReg.y, aReg.y);
        AdU[(ac + 2) * 64 + ar] = pack2(aReg.z, aReg.z);
        AdU[(ac + 3) * 64 + ar] = pack2(aReg.w, aReg.w);
    }
    cpwaitall();
    __syncthreads();

    #pragma unroll 2
    for (int c = 0; c < 16; ++c) {
        const int cur = c & 1;
        const int nxt = cur ^ 1;
        if (c + 1 < 16) {   // issue next chunk's loads (latency hidden by compute)
            aReg = *(const float4*)(aPtr + (c + 1) * 16);
            const float* wp = wPtr + (long)(c + 1) * 16 * F_;
            uint32_t wd = s2u(&sm->Ws[nxt][wf][wg]);
            cpasync16(wd,      wp);
            cpasync16(wd + 16, wp + 4);
            cpasync16(wd + 32, wp + 8);
            cpasync16(wd + 48, wp + 12);
            cpcommit();
        }
        const u64* AdU = (const u64*)sm->Ad[cur];
        const u64* WsU = (const u64*)sm->Ws[cur];
        #pragma unroll
        for (int f = 0; f < 16; ++f) {
            u64 ad[8], bs[4];
            const ulonglong2* ap2 = (const ulonglong2*)(AdU + f * 64 + tb * 8);
            ulonglong2 v0 = ap2[0], v1 = ap2[1], v2 = ap2[2], v3 = ap2[3];
            ad[0] = v0.x; ad[1] = v0.y; ad[2] = v1.x; ad[3] = v1.y;
            ad[4] = v2.x; ad[5] = v2.y; ad[6] = v3.x; ad[7] = v3.y;
            const ulonglong2* bp2 = (const ulonglong2*)(WsU + f * 128 + tg * 4);
            ulonglong2 w0 = bp2[0], w1 = bp2[1];
            bs[0] = w0.x; bs[1] = w0.y; bs[2] = w1.x; bs[3] = w1.y;
            #pragma unroll
            for (int i = 0; i < 8; i++) {
                fma2(acc[i][0], ad[i], bs[0]);
                fma2(acc[i][1], ad[i], bs[1]);
                fma2(acc[i][2], ad[i], bs[2]);
                fma2(acc[i][3], ad[i], bs[3]);
            }
        }
        if (c + 1 < 16) {
            u64* AdU2 = (u64*)sm->Ad[nxt];
            AdU2[(ac + 0) * 64 + ar] = pack2(aReg.x, aReg.x);
            AdU2[(ac + 1) * 64 + ar] = pack2(aReg.y, aReg.y);
            AdU2[(ac + 2) * 64 + ar] = pack2(aReg.z, aReg.z);
            AdU2[(ac + 3) * 64 + ar] = pack2(aReg.w, aReg.w);
            cpwaitall();
        }
        __syncthreads();
    }
}

__device__ __forceinline__ void unpack8(const u64 a[4], float c[8]) {
    unpack2(a[0], c[0], c[1]);
    unpack2(a[1], c[2], c[3]);
    unpack2(a[2], c[4], c[5]);
    unpack2(a[3], c[6], c[7]);
}

// ---------------- K1: QWq[b,n,g] = Q[b,n,:]@Wq[n] + bq[n,:] ----------------
__global__ void __launch_bounds__(256, 2) k_qwq(const float* __restrict__ Q,
                                                const float* __restrict__ Wq,
                                                const float* __restrict__ bq)
{
    __shared__ Smem sm;
    const int n = blockIdx.x;
    u64 acc[8][4];
    gemm_tile(Q + (size_t)n * F_, (long)N_ * F_, Wq + (size_t)n * F_ * F_, &sm, acc);
    const int t = threadIdx.x, tb = t >> 5, tg = t & 31;
    const float* bqp = bq + (size_t)n * F_ + tg * 8;
    float4 b0 = *(const float4*)bqp, b1 = *(const float4*)(bqp + 4);
    #pragma unroll
    for (int i = 0; i < 8; i++) {
        float c[8]; unpack8(acc[i], c);
        float4 o0 = make_float4(c[0] + b0.x, c[1] + b0.y, c[2] + b0.z, c[3] + b0.w);
        float4 o1 = make_float4(c[4] + b1.x, c[5] + b1.y, c[6] + b1.z, c[7] + b1.w);
        float* op = g_QWq + ((size_t)(tb * 8 + i) * N_ + n) * F_ + tg * 8;
        *(float4*)op = o0; *(float4*)(op + 4) = o1;
    }
}

// ---------------- K2: per (h,n) CTA: logits + VWv ----------------
__global__ void __launch_bounds__(256, 2) k_kv(const float* __restrict__ Kt,
                                               const float* __restrict__ Vt,
                                               const float* __restrict__ Wk,
                                               const float* __restrict__ bk,
                                               const float* __restrict__ Wv,
                                               const float* __restrict__ bv)
{
    __shared__ Smem sm;
    const int h = blockIdx.x, n = blockIdx.y;
    const int t = threadIdx.x, tb = t >> 5, tg = t & 31;
    u64 acc[8][4];

    // ---- Phase 1: C = K[:,h,n,:] @ Wk[n,h]; logits = rowdot(C+bk, QWq) ----
    gemm_tile(Kt + ((size_t)h * N_ + n) * F_, (long)H_ * N_ * F_,
              Wk + ((size_t)n * H_ + h) * F_ * F_, &sm, acc);
    {
        const float* bkp = bk + ((size_t)n * H_ + h) * F_ + tg * 8;
        float4 k0 = *(const float4*)bkp, k1 = *(const float4*)(bkp + 4);
        float part[8];
        #pragma unroll
        for (int i = 0; i < 8; i++) {
            float c[8]; unpack8(acc[i], c);
            const float* qp = g_QWq + ((size_t)(tb * 8 + i) * N_ + n) * F_ + tg * 8;
            float4 q0 = *(const float4*)qp, q1 = *(const float4*)(qp + 4);
            part[i] = (c[0] + k0.x) * q0.x + (c[1] + k0.y) * q0.y
                    + (c[2] + k0.z) * q0.z + (c[3] + k0.w) * q0.w
                    + (c[4] + k1.x) * q1.x + (c[5] + k1.y) * q1.y
                    + (c[6] + k1.z) * q1.z + (c[7] + k1.w) * q1.w;
        }
        #pragma unroll
        for (int off = 16; off > 0; off >>= 1)
            #pragma unroll
            for (int i = 0; i < 8; i++)
                part[i] += __shfl_xor_sync(0xffffffffu, part[i], off);
        if (tg == 0) {
            #pragma unroll
            for (int i = 0; i < 8; i++)
                g_logits[((size_t)(tb * 8 + i) * N_ + n) * H_ + h] = part[i];
        }
    }
    __syncthreads();

    // ---- Phase 2: VWv[b,n,h,:] = V[:,h,n,:] @ Wv[n,h] + bv ----
    gemm_tile(Vt + ((size_t)h * N_ + n) * F_, (long)H_ * N_ * F_,
              Wv + ((size_t)n * H_ + h) * F_ * F_, &sm, acc);
    {
        const float* bvp = bv + ((size_t)n * H_ + h) * F_ + tg * 8;
        float4 v0 = *(const float4*)bvp, v1 = *(const float4*)(bvp + 4);
        #pragma unroll
        for (int i = 0; i < 8; i++) {
            float c[8]; unpack8(acc[i], c);
            float4 o0 = make_float4(c[0] + v0.x, c[1] + v0.y, c[2] + v0.z, c[3] + v0.w);
            float4 o1 = make_float4(c[4] + v1.x, c[5] + v1.y, c[6] + v1.z, c[7] + v1.w);
            float* op = g_VWv + (((size_t)(tb * 8 + i) * N_ + n) * H_ + h) * F_ + tg * 8;
            *(float4*)op = o0; *(float4*)(op + 4) = o1;
        }
    }
}

// ---------------- K3: softmax over H; write scores to d_out ----------------
__global__ void k_softmax(float* __restrict__ out)
{
    const int idx = blockIdx.x * 256 + threadIdx.x;   // (b*N+n), 0..2047
    const float* lp = g_logits + (size_t)idx * H_;
    float l[H_];
    float m = -3.4e38f;
    #pragma unroll
    for (int h = 0; h < H_; ++h) { l[h] = lp[h]; m = fmaxf(m, l[h]); }
    float s = 0.f;
    #pragma unroll
    for (int h = 0; h < H_; ++h) { l[h] = expf(l[h] - m); s += l[h]; }
    const float inv = 1.0f / s;
    float* sp = out + (size_t)B_ * N_ * F_ + (size_t)idx * H_;
    #pragma unroll
    for (int h = 0; h < H_; ++h) sp[h] = l[h] * inv;
}

// ---------------- K4: heads[b,n,g] = sum_h scores * VWv ----------------
__global__ void k_heads(float* __restrict__ out)
{
    __shared__ float s[H_];
    const int bn = blockIdx.x;          // b*N+n
    const int g = threadIdx.x;          // 0..255
    if (g < H_) s[g] = out[(size_t)B_ * N_ * F_ + (size_t)bn * H_ + g];
    __syncthreads();
    const float* vp = g_VWv + (size_t)bn * H_ * F_ + g;
    float acc = 0.f;
    #pragma unroll
    for (int h = 0; h < H_; ++h) acc += s[h] * vp[(size_t)h * F_];
    out[(size_t)bn * F_ + g] = acc;
}

// ---------------- Launch ----------------
extern "C" void kernel_launch(void* const* d_in, const int* in_sizes, int n_in,
                              void* d_out, int out_size)
{
    (void)in_sizes; (void)n_in; (void)out_size;
    const float* Q  = (const float*)d_in[0];
    const float* K  = (const float*)d_in[1];
    const float* V  = (const float*)d_in[2];
    const float* Wq = (const float*)d_in[3];
    const float* bq = (const float*)d_in[4];
    const float* Wk = (const float*)d_in[5];
    const float* bk = (const float*)d_in[6];
    const float* Wv = (const float*)d_in[7];
    const float* bv = (const float*)d_in[8];
    float* out = (float*)d_out;

    k_qwq<<<N_, 256>>>(Q, Wq, bq);
    k_kv<<<dim3(H_, N_), 256>>>(K, V, Wk, bk, Wv, bv);
    k_softmax<<<(B_ * N_) / 256, 256>>>(out);
    k_heads<<<B_ * N_, 256>>>(out);
}

// round 6
// speedup vs baseline: 1.8654x; 1.8649x over previous
#include <cuda_runtime.h>
#include <cuda_bf16.h>
#include <cstdint>

#define B_ 64
#define N_ 32
#define H_ 24
#define F_ 256

// ---------------- scratch ----------------
__device__ float g_QWq[(size_t)B_ * N_ * F_];              // [b][n][g]
__device__ float g_KWk[(size_t)B_ * N_ * H_ * F_];         // [b][n][h][g]
__device__ float g_VWv[(size_t)B_ * N_ * H_ * F_];         // [b][n][h][g]

// ---------------- helpers ----------------
__device__ __forceinline__ uint32_t s2u(const void* p) {
    return (uint32_t)__cvta_generic_to_shared(p);
}
__device__ __forceinline__ void cpasync16(uint32_t dst, const void* src) {
    asm volatile("cp.async.cg.shared.global [%0], [%1], 16;" :: "r"(dst), "l"(src));
}
__device__ __forceinline__ void cpcommit() { asm volatile("cp.async.commit_group;"); }
__device__ __forceinline__ void cpwait1() { asm volatile("cp.async.wait_group 1;" ::: "memory"); }
__device__ __forceinline__ void cpwait0() { asm volatile("cp.async.wait_all;" ::: "memory"); }

__device__ __forceinline__ uint32_t bpack(float a, float b, float& ra, float& rb) {
    __nv_bfloat16 ha = __float2bfloat16(a), hb = __float2bfloat16(b);
    ra = a - __bfloat162float(ha);
    rb = b - __bfloat162float(hb);
    return (uint32_t)__bfloat16_as_ushort(ha) | ((uint32_t)__bfloat16_as_ushort(hb) << 16);
}
__device__ __forceinline__ uint32_t bpack1(float a, float b) {
    __nv_bfloat16 ha = __float2bfloat16(a), hb = __float2bfloat16(b);
    return (uint32_t)__bfloat16_as_ushort(ha) | ((uint32_t)__bfloat16_as_ushort(hb) << 16);
}
__device__ __forceinline__ uint2 lds64(uint32_t a) {
    uint2 r;
    asm volatile("ld.shared.v2.u32 {%0,%1}, [%2];" : "=r"(r.x), "=r"(r.y) : "r"(a));
    return r;
}
// mma m16n8k16 bf16: a-regs (a0,a1,a2,a3) = (rA.x, rA8.x, rA.y, rA8.y)
__device__ __forceinline__ void mma4(float* c, uint2 rA, uint2 rA8, uint2 b) {
    asm volatile("mma.sync.aligned.m16n8k16.row.col.f32.bf16.bf16.f32 "
                 "{%0,%1,%2,%3}, {%4,%5,%6,%7}, {%8,%9}, {%0,%1,%2,%3};"
                 : "+f"(c[0]), "+f"(c[1]), "+f"(c[2]), "+f"(c[3])
                 : "r"(rA.x), "r"(rA8.x), "r"(rA.y), "r"(rA8.y), "r"(b.x), "r"(b.y));
}

// smem offsets (bytes)
#define OFF_WRAW 0        // 2 x 16384 fp32 W chunk
#define OFF_ARAW 32768    // 2 x 4096  fp32 A chunk
#define OFF_WH   40960    // 8192: bf16 W hi [256 g][8 words interleaved]
#define OFF_WL   49152    // 8192: bf16 W lo
#define OFF_AH   57344    // 2048: bf16 A hi [64 r][8 words]
#define OFF_AL   59392    // 2048
#define SMEM_SZ  61440

// Core: C[64][256] = A[64x256] @ W[256x256] (+bias), P passes, HMMA bf16 3-term
template <int P>
__device__ __forceinline__ void proj_gemm(
    char* smk, uint32_t sb,
    const float* A0, const float* A1, long sA,
    const float* W0, const float* W1,
    const float* b0, const float* b1,
    float* o0, float* o1, long pitch)
{
    const int t = threadIdx.x;
    const int w = t >> 5, l = t & 31;
    const int mhalf = w >> 2, wq = w & 3;
    const int c = l & 3;
    const uint32_t x = ((l >> 4) & 1) << 2;        // frag-read XOR (bit2 of row/col)

    float acc[2][8][4];
    #pragma unroll
    for (int i = 0; i < 2; i++)
        #pragma unroll
        for (int j = 0; j < 8; j++)
            #pragma unroll
            for (int k = 0; k < 4; k++) acc[i][j][k] = 0.f;

    // prefetch chunk gc into raw buffer gc&1
    auto prefetch = [&](int gc) {
        const int pass = gc >> 4, cc = gc & 15, buf = gc & 1;
        const float* Wp = ((P == 1 || pass == 0) ? W0 : W1) + (size_t)cc * 16 * F_;
        const float* Ap = ((P == 1 || pass == 0) ? A0 : A1);
        uint32_t wd = sb + OFF_WRAW + buf * 16384;
        #pragma unroll
        for (int q = 0; q < 4; ++q)
            cpasync16(wd + q * 4096 + t * 16, Wp + q * 1024 + t * 4);
        const int r = t >> 2, q = t & 3;
        cpasync16(sb + OFF_ARAW + buf * 4096 + t * 16,
                  Ap + (long)r * sA + cc * 16 + q * 4);
        cpcommit();
    };

    prefetch(0);
    prefetch(1);

    for (int gc = 0; gc < 16 * P; ++gc) {
        const int buf = gc & 1;
        if (gc + 1 < 16 * P) cpwait1(); else cpwait0();
        __syncthreads();

        // ---- convert W chunk: wraw[f][g] -> WH/WL[g][interleaved f-words] ----
        {
            const float* wr = (const float*)(smk + OFF_WRAW + buf * 16384);
            float v[16];
            #pragma unroll
            for (int f = 0; f < 16; ++f) v[f] = wr[f * 256 + t];
            uint32_t hi[8], lo[8];
            #pragma unroll
            for (int j = 0; j < 8; ++j) {
                float ra, rb;
                hi[j] = bpack(v[2 * j], v[2 * j + 1], ra, rb);
                lo[j] = bpack1(ra, rb);
            }
            // physical word p: content fp with iw(fp) = fp<4 ? 2fp : 2fp-7;
            // halves swapped when (g>>2)&1
            const int s0 = ((t >> 2) & 1) << 4;
            char* bh = smk + OFF_WH + t * 32;
            char* bl = smk + OFF_WL + t * 32;
            *(uint4*)(bh + s0)        = make_uint4(hi[0], hi[4], hi[1], hi[5]);
            *(uint4*)(bh + (16 ^ s0)) = make_uint4(hi[2], hi[6], hi[3], hi[7]);
            *(uint4*)(bl + s0)        = make_uint4(lo[0], lo[4], lo[1], lo[5]);
            *(uint4*)(bl + (16 ^ s0)) = make_uint4(lo[2], lo[6], lo[3], lo[7]);
        }
        // ---- convert A chunk: araw[r][f] -> AH/AL ----
        {
            const int r = t >> 2, q = t & 3;
            float4 v = *(const float4*)(smk + OFF_ARAW + buf * 4096 + t * 16);
            float r0, r1, r2, r3;
            uint32_t h0 = bpack(v.x, v.y, r0, r1);
            uint32_t h1 = bpack(v.z, v.w, r2, r3);
            uint32_t l0 = bpack1(r0, r1);
            uint32_t l1 = bpack1(r2, r3);
            const int iw0 = (q < 2) ? 4 * q : 4 * q - 7;
            const int iw1 = (q < 2) ? 4 * q + 2 : 4 * q - 5;
            const int x4 = ((r >> 2) & 1) << 2;
            char* ah = smk + OFF_AH + r * 32;
            char* al = smk + OFF_AL + r * 32;
            *(uint32_t*)(ah + ((iw0 ^ x4) << 2)) = h0;
            *(uint32_t*)(ah + ((iw1 ^ x4) << 2)) = h1;
            *(uint32_t*)(al + ((iw0 ^ x4) << 2)) = l0;
            *(uint32_t*)(al + ((iw1 ^ x4) << 2)) = l1;
        }
        __syncthreads();

        if (gc + 2 < 16 * P) prefetch(gc + 2);

        // ---- HMMA: 2 m-tiles x 8 n-tiles x 3 terms ----
        const uint32_t woff = ((2 * c) ^ x) << 2;
        #pragma unroll
        for (int mt = 0; mt < 2; ++mt) {
            const int r1 = mhalf * 32 + mt * 16 + (l >> 2);
            uint2 ah  = lds64(sb + OFF_AH + r1 * 32 + woff);
            uint2 ah8 = lds64(sb + OFF_AH + (r1 + 8) * 32 + woff);
            uint2 al  = lds64(sb + OFF_AL + r1 * 32 + woff);
            uint2 al8 = lds64(sb + OFF_AL + (r1 + 8) * 32 + woff);
            #pragma unroll
            for (int nt = 0; nt < 8; ++nt) {
                const int g = wq * 64 + nt * 8 + (l >> 2);
                uint2 bh = lds64(sb + OFF_WH + g * 32 + woff);
                uint2 bl = lds64(sb + OFF_WL + g * 32 + woff);
                mma4(acc[mt][nt], ah, ah8, bh);
                mma4(acc[mt][nt], ah, ah8, bl);
                mma4(acc[mt][nt], al, al8, bh);
            }
        }

        // ---- epilogue at end of each pass ----
        if ((gc & 15) == 15) {
            const int pass = gc >> 4;
            const float* bb = (P == 1 || pass == 0) ? b0 : b1;
            float* ob = (P == 1 || pass == 0) ? o0 : o1;
            #pragma unroll
            for (int nt = 0; nt < 8; ++nt) {
                const int g0 = wq * 64 + nt * 8 + 2 * c;
                const float2 bv = *(const float2*)(bb + g0);
                #pragma unroll
                for (int mt = 0; mt < 2; ++mt) {
                    const int r1 = mhalf * 32 + mt * 16 + (l >> 2);
                    float2 v0, v1;
                    v0.x = acc[mt][nt][0] + bv.x; v0.y = acc[mt][nt][1] + bv.y;
                    v1.x = acc[mt][nt][2] + bv.x; v1.y = acc[mt][nt][3] + bv.y;
                    *(float2*)(ob + (long)r1 * pitch + g0) = v0;
                    *(float2*)(ob + (long)(r1 + 8) * pitch + g0) = v1;
                    acc[mt][nt][0] = acc[mt][nt][1] = 0.f;
                    acc[mt][nt][2] = acc[mt][nt][3] = 0.f;
                }
            }
        }
    }
}

// ---------------- kernels ----------------
__global__ void __launch_bounds__(256, 2) k_kv(const float* __restrict__ Kt,
                                               const float* __restrict__ Vt,
                                               const float* __restrict__ Wk,
                                               const float* __restrict__ bk,
                                               const float* __restrict__ Wv,
                                               const float* __restrict__ bv)
{
    extern __shared__ char smk[];
    const int h = blockIdx.x, n = blockIdx.y;
    const size_t nh = (size_t)n * H_ + h;
    proj_gemm<2>(smk, s2u(smk),
                 Kt + ((size_t)h * N_ + n) * F_, Vt + ((size_t)h * N_ + n) * F_,
                 (long)H_ * N_ * F_,
                 Wk + nh * F_ * F_, Wv + nh * F_ * F_,
                 bk + nh * F_, bv + nh * F_,
                 g_KWk + nh * F_, g_VWv + nh * F_,
                 (long)N_ * H_ * F_);
}

__global__ void __launch_bounds__(256, 2) k_qwq(const float* __restrict__ Q,
                                                const float* __restrict__ Wq,
                                                const float* __restrict__ bq)
{
    extern __shared__ char smk[];
    const int n = blockIdx.x;
    proj_gemm<1>(smk, s2u(smk),
                 Q + (size_t)n * F_, Q + (size_t)n * F_,
                 (long)N_ * F_,
                 Wq + (size_t)n * F_ * F_, Wq + (size_t)n * F_ * F_,
                 bq + (size_t)n * F_, bq + (size_t)n * F_,
                 g_QWq + (size_t)n * F_, g_QWq + (size_t)n * F_,
                 (long)N_ * F_);
}

// logits + softmax: one warp per (b,n)
__global__ void __launch_bounds__(256) k_logits(float* __restrict__ out)
{
    const int w = threadIdx.x >> 5, l = threadIdx.x & 31;
    const int wi = blockIdx.x * 8 + w;     // b*32+n
    const int b = wi >> 5, n = wi & 31;
    const float* qp = g_QWq + ((size_t)b * N_ + n) * F_;
    float q[8];
    #pragma unroll
    for (int j = 0; j < 8; ++j) q[j] = qp[j * 32 + l];

    const float* kp = g_KWk + ((size_t)b * N_ + n) * H_ * F_;
    float my = -3.4e38f;
    #pragma unroll 1
    for (int h = 0; h < H_; ++h) {
        const float* kr = kp + (size_t)h * F_;
        float d = 0.f;
        #pragma unroll
        for (int j = 0; j < 8; ++j) d += q[j] * kr[j * 32 + l];
        #pragma unroll
        for (int off = 16; off > 0; off >>= 1)
            d += __shfl_xor_sync(0xffffffffu, d, off);
        if (l == h) my = d;
    }
    float m = my;
    #pragma unroll
    for (int off = 16; off > 0; off >>= 1)
        m = fmaxf(m, __shfl_xor_sync(0xffffffffu, m, off));
    float e = (l < H_) ? expf(my - m) : 0.f;
    float s = e;
    #pragma unroll
    for (int off = 16; off > 0; off >>= 1)
        s += __shfl_xor_sync(0xffffffffu, s, off);
    if (l < H_)
        out[(size_t)B_ * N_ * F_ + (size_t)wi * H_ + l] = e / s;
}

// heads[b][n][g] = sum_h scores * VWv[b][n][h][g]
__global__ void __launch_bounds__(256) k_heads(float* __restrict__ out)
{
    __shared__ float s[H_];
    const int bn = blockIdx.x;
    const int g = threadIdx.x;
    if (g < H_) s[g] = out[(size_t)B_ * N_ * F_ + (size_t)bn * H_ + g];
    __syncthreads();
    const float* vp = g_VWv + (size_t)bn * H_ * F_ + g;
    float a = 0.f;
    #pragma unroll
    for (int h = 0; h < H_; ++h) a += s[h] * vp[(size_t)h * F_];
    out[(size_t)bn * F_ + g] = a;
}

// ---------------- launch ----------------
extern "C" void kernel_launch(void* const* d_in, const int* in_sizes, int n_in,
                              void* d_out, int out_size)
{
    (void)in_sizes; (void)n_in; (void)out_size;
    const float* Q  = (const float*)d_in[0];
    const float* K  = (const float*)d_in[1];
    const float* V  = (const float*)d_in[2];
    const float* Wq = (const float*)d_in[3];
    const float* bq = (const float*)d_in[4];
    const float* Wk = (const float*)d_in[5];
    const float* bk = (const float*)d_in[6];
    const float* Wv = (const float*)d_in[7];
    const float* bv = (const float*)d_in[8];
    float* out = (float*)d_out;

    static int attr_done = 0;
    if (!attr_done) {
        cudaFuncSetAttribute(k_kv, cudaFuncAttributeMaxDynamicSharedMemorySize, SMEM_SZ);
        cudaFuncSetAttribute(k_qwq, cudaFuncAttributeMaxDynamicSharedMemorySize, SMEM_SZ);
        attr_done = 1;
    }

    k_qwq<<<N_, 256, SMEM_SZ>>>(Q, Wq, bq);
    k_kv<<<dim3(H_, N_), 256, SMEM_SZ>>>(K, V, Wk, bk, Wv, bv);
    k_logits<<<(B_ * N_) / 8, 256>>>(out);
    k_heads<<<B_ * N_, 256>>>(out);
}